// round 14
// baseline (speedup 1.0000x reference)
#include <cuda_runtime.h>
#include <cuda_bf16.h>
#include <cstdint>

#define B_GR   8192
#define NPG    39
#define N_TOT  (B_GR*NPG)
#define DEG    8
#define EPG    (NPG*DEG)          /* 312 */
#define E_TOT  (N_TOT*DEG)        /* 2555904 */
#define TE     (EPG+NPG)          /* 351 */
#define FDIM   4560
#define KPAD   4608

// ---------------- scratch (static device globals, zero-initialized) -------
__device__ __align__(256) __nv_bfloat16 g_fh [(size_t)B_GR*KPAD];
__device__ __align__(256) __nv_bfloat16 g_fl [(size_t)B_GR*KPAD];
__device__ __align__(256) __nv_bfloat16 g_bth[(size_t)1024*KPAD];
__device__ __align__(256) __nv_bfloat16 g_btl[(size_t)1024*KPAD];
__device__ __align__(256) __nv_bfloat16 g_bt2h[(size_t)128*1024];
__device__ __align__(256) __nv_bfloat16 g_bt2l[(size_t)128*1024];
__device__ __align__(256) __nv_bfloat16 g_h1h[(size_t)B_GR*1024];
__device__ __align__(256) __nv_bfloat16 g_h1l[(size_t)B_GR*1024];
__device__ __align__(256) float g_h2[(size_t)B_GR*128];
__device__ __align__(256) float g_ha[(size_t)N_TOT*64];
__device__ __align__(256) float g_hb[(size_t)N_TOT*64];
__device__ __align__(256) float g_sn[N_TOT];
__device__ __align__(256) float g_dn[N_TOT];
__device__ __align__(256) unsigned char  g_csrc[(size_t)B_GR*352];
__device__ __align__(256) unsigned char  g_cdst[(size_t)B_GR*352];
__device__ __align__(256) unsigned short g_cstart[(size_t)B_GR*40];
__device__ int   g_is64;

// ---------------- PTX helpers (baseline sm_80-class only) ------------------
__device__ __forceinline__ uint32_t smem_u32(const void* p) {
    uint32_t a;
    asm("{ .reg .u64 t; cvta.to.shared.u64 t, %1; cvt.u32.u64 %0, t; }" : "=r"(a) : "l"(p));
    return a;
}
#define CP_ASYNC16(sa, ga) \
    asm volatile("cp.async.cg.shared.global [%0], [%1], 16;" :: "r"(sa), "l"(ga))
#define CP_COMMIT()  asm volatile("cp.async.commit_group;" ::: "memory")
#define CP_WAIT(n)   asm volatile("cp.async.wait_group %0;" :: "n"(n) : "memory")

#define LDSM4(r, addr) \
    asm volatile("ldmatrix.sync.aligned.m8n8.x4.shared.b16 {%0,%1,%2,%3}, [%4];" \
        : "=r"((r)[0]), "=r"((r)[1]), "=r"((r)[2]), "=r"((r)[3]) : "r"(addr))

#define MMA_BF16(acc, a, b) \
    asm volatile("mma.sync.aligned.m16n8k16.row.col.f32.bf16.bf16.f32 " \
        "{%0,%1,%2,%3}, {%4,%5,%6,%7}, {%8,%9}, {%0,%1,%2,%3};" \
        : "+f"((acc)[0]), "+f"((acc)[1]), "+f"((acc)[2]), "+f"((acc)[3]) \
        : "r"((a)[0]), "r"((a)[1]), "r"((a)[2]), "r"((a)[3]), \
          "r"((b)[0]), "r"((b)[1]))

__device__ __forceinline__ void put2(__nv_bfloat16* fh, __nv_bfloat16* fl, size_t idx, float v) {
    __nv_bfloat16 h = __float2bfloat16(v);
    fh[idx] = h;
    fl[idx] = __float2bfloat16(v - __bfloat162float(h));
}

// ---------------- edge dtype detection ------------------------------------
__global__ void detect_kernel(const unsigned* __restrict__ e) {
    int any = __syncthreads_or(e[2*threadIdx.x + 1] != 0u);
    if (threadIdx.x == 0) g_is64 = any ? 0 : 1;
}

// ---------------- transpose + split W[KDIM,NDIM] -> out[NDIM,KP] hi/lo -----
template<int KDIM, int NDIM, int KP>
__global__ __launch_bounds__(256) void tsplit_kernel(const float* __restrict__ W,
                                                     __nv_bfloat16* __restrict__ bh,
                                                     __nv_bfloat16* __restrict__ bl) {
    __shared__ __align__(16) float tile[32][33];
    int kb = blockIdx.y * 32, nb = blockIdx.x * 32;
    int tx = threadIdx.x, ty = threadIdx.y;
    for (int i = ty; i < 32; i += 8) {
        int k = kb + i;
        tile[i][tx] = (k < KDIM) ? W[(size_t)k*NDIM + nb + tx] : 0.f;
    }
    __syncthreads();
    for (int i = ty; i < 32; i += 8) {
        int n = nb + i, k = kb + tx;
        if (k < KDIM) put2(bh, bl, (size_t)n*KP + k, tile[tx][i]);
    }
}

// ---------------- prep: CSR build (deterministic) + res0/pool0 -------------
__global__ __launch_bounds__(64) void prep_kernel(
    const float* __restrict__ x, const void* __restrict__ edges,
    unsigned char* __restrict__ csrc, unsigned char* __restrict__ cdst,
    unsigned short* __restrict__ cstart,
    __nv_bfloat16* __restrict__ fh, __nv_bfloat16* __restrict__ fl)
{
    __shared__ __align__(16) unsigned char es[TE], ed[TE];
    __shared__ __align__(16) int cnt[NPG];
    __shared__ __align__(16) unsigned short st[NPG+1];
    const int g = blockIdx.x, tid = threadIdx.x;
    const int is64 = g_is64;
    const long ebase = (long)g*EPG;
    if (tid < NPG) cnt[tid] = 0;
    for (int i = tid; i < EPG; i += 64) {
        int s, d;
        if (is64) { const long long* e=(const long long*)edges; s=(int)e[ebase+i]; d=(int)e[(long)E_TOT+ebase+i]; }
        else      { const int* e=(const int*)edges; s=e[ebase+i]; d=e[(long)E_TOT+ebase+i]; }
        es[i]=(unsigned char)(s-g*NPG); ed[i]=(unsigned char)(d-g*NPG);
    }
    for (int i = EPG+tid; i < TE; i += 64) { es[i]=ed[i]=(unsigned char)(i-EPG); }
    __syncthreads();
    for (int i = tid; i < TE; i += 64) atomicAdd(&cnt[ed[i]], 1);
    __syncthreads();
    if (tid == 0) {
        int run = 0;
        for (int d = 0; d < NPG; d++) { st[d]=(unsigned short)run; run += cnt[d]; }
        st[NPG] = (unsigned short)run;
    }
    __syncthreads();
    if (tid < NPG) {                     // deterministic scatter per dst
        int pos = st[tid];
        for (int i = 0; i < TE; i++)
            if (ed[i] == (unsigned char)tid) {
                csrc[(size_t)g*352 + pos] = es[i];
                cdst[(size_t)g*352 + pos] = (unsigned char)tid;
                pos++;
            }
    }
    if (tid < NPG+1) cstart[(size_t)g*40 + tid] = st[tid];
    if (tid < NPG)   put2(fh, fl, (size_t)g*KPAD + tid, x[g*NPG + tid]);
    if (tid == 0) {
        float m = x[g*NPG];
        for (int n = 1; n < NPG; n++) m = fmaxf(m, x[g*NPG + n]);
        put2(fh, fl, (size_t)g*KPAD + 4446, m);
    }
}

// ---------------- layer A: dense H = hprev @ W, s/d logits -----------------
template<int Fi, int Fo>
__global__ __launch_bounds__(256) void layerA_kernel(
    const float* __restrict__ hprev, const float* __restrict__ W,
    const float* __restrict__ a_s, const float* __restrict__ a_d,
    float* __restrict__ H, float* __restrict__ sN, float* __restrict__ dN)
{
    constexpr int NB = 128;
    __shared__ __align__(16) float wS[Fi*Fo];
    __shared__ __align__(16) float asS[Fo];
    __shared__ __align__(16) float adS[Fo];
    __shared__ __align__(16) float xS[NB*Fi];
    __shared__ __align__(16) float htmp[(Fo % 4 == 0) ? 4 : NB*Fo];
    const int tid = threadIdx.x;
    const size_t n0 = (size_t)blockIdx.x * NB;

    for (int i = tid; i < Fi*Fo; i += 256) wS[i] = W[i];
    if (tid < Fo) { asS[tid] = a_s[tid]; adS[tid] = a_d[tid]; }
    for (int i = tid; i < NB*Fi/4; i += 256)
        *(float4*)&xS[i*4] = *(const float4*)&hprev[n0*Fi + i*4];
    __syncthreads();

    if constexpr (Fo % 4 == 0) {
        constexpr int C4 = Fo/4;
        const int lane = tid & 31;
        for (int it = tid; it < NB*C4; it += 256) {
            int n = it / C4, c4 = (it % C4)*4;
            float4 acc = make_float4(0.f,0.f,0.f,0.f);
            #pragma unroll
            for (int ci = 0; ci < Fi; ci++) {
                float a = xS[n*Fi + ci];
                const float4 w = *(const float4*)&wS[ci*Fo + c4];
                acc.x=fmaf(a,w.x,acc.x); acc.y=fmaf(a,w.y,acc.y);
                acc.z=fmaf(a,w.z,acc.z); acc.w=fmaf(a,w.w,acc.w);
            }
            *(float4*)&H[(n0+n)*Fo + c4] = acc;
            float sp = acc.x*asS[c4] + acc.y*asS[c4+1] + acc.z*asS[c4+2] + acc.w*asS[c4+3];
            float dp = acc.x*adS[c4] + acc.y*adS[c4+1] + acc.z*adS[c4+2] + acc.w*adS[c4+3];
            #pragma unroll
            for (int off = C4/2; off > 0; off >>= 1) {
                sp += __shfl_xor_sync(0xffffffffu, sp, off);
                dp += __shfl_xor_sync(0xffffffffu, dp, off);
            }
            if ((lane & (C4-1)) == 0) { sN[n0+n] = sp; dN[n0+n] = dp; }
        }
    } else {
        for (int it = tid; it < NB*Fo; it += 256) {
            int n = it / Fo, c = it % Fo;
            float acc = 0.f;
            #pragma unroll
            for (int ci = 0; ci < Fi; ci++) acc = fmaf(xS[n*Fi+ci], wS[ci*Fo+c], acc);
            H[(n0+n)*Fo + c] = acc;
            htmp[n*Fo + c] = acc;
        }
        __syncthreads();
        if (tid < NB) {
            float s = 0.f, d = 0.f;
            #pragma unroll
            for (int c = 0; c < Fo; c++) { float v = htmp[tid*Fo+c]; s = fmaf(v, asS[c], s); d = fmaf(v, adS[c], d); }
            sN[n0+tid] = s; dN[n0+tid] = d;
        }
    }
}

// ---------------- layer B: per-graph softmax + aggregate -------------------
template<int Fo, bool HNEXT>
__global__ __launch_bounds__(128) void layerB_kernel(
    const float* __restrict__ H, const float* __restrict__ sN, const float* __restrict__ dN,
    const unsigned char* __restrict__ csrc, const unsigned char* __restrict__ cdst,
    const unsigned short* __restrict__ cstart,
    const float* __restrict__ bvec, float* __restrict__ hnext,
    __nv_bfloat16* __restrict__ fh, __nv_bfloat16* __restrict__ fl,
    int resOff, int poolOff)
{
    __shared__ __align__(16) float hS[NPG*Fo];
    __shared__ __align__(16) float oS[NPG*Fo];
    __shared__ __align__(16) float eW[TE];
    __shared__ __align__(16) float snS[NPG];
    __shared__ __align__(16) float dnS[NPG];
    __shared__ __align__(16) float denS[NPG];
    __shared__ __align__(16) float biasS[Fo];
    __shared__ __align__(16) unsigned char srcS[TE];
    __shared__ __align__(16) unsigned char dstS[TE];
    __shared__ __align__(16) unsigned short stS[NPG+1];
    const int tid = threadIdx.x;
    const int g = blockIdx.x;
    const size_t nb = (size_t)g * NPG;

    if constexpr (Fo % 4 == 0) {
        for (int i = tid; i < NPG*Fo/4; i += 128)
            *(float4*)&hS[i*4] = *(const float4*)&H[nb*Fo + i*4];
    } else {
        for (int i = tid; i < NPG*Fo; i += 128) hS[i] = H[nb*Fo + i];
    }
    if (tid < NPG)   { snS[tid] = sN[nb+tid]; dnS[tid] = dN[nb+tid]; }
    if (tid < Fo)    biasS[tid] = bvec[tid];
    if (tid < NPG+1) stS[tid] = cstart[(size_t)g*40 + tid];
    for (int i = tid; i < TE; i += 128) {
        srcS[i] = csrc[(size_t)g*352 + i];
        dstS[i] = cdst[(size_t)g*352 + i];
    }
    __syncthreads();

    for (int i = tid; i < TE; i += 128) {
        float e = snS[srcS[i]] + dnS[dstS[i]];
        eW[i] = e > 0.f ? e : 0.2f*e;
    }
    __syncthreads();

    if (tid < NPG) {
        int s0 = stS[tid], s1 = stS[tid+1];
        float m = -3.0e38f;
        for (int j = s0; j < s1; j++) m = fmaxf(m, eW[j]);
        float dd = 0.f;
        for (int j = s0; j < s1; j++) { float w = __expf(eW[j] - m); eW[j] = w; dd += w; }
        denS[tid] = dd;
    }
    __syncthreads();

    const size_t fbase = (size_t)g*KPAD + resOff;
    if constexpr (Fo % 4 == 0) {
        constexpr int C4 = Fo/4;
        for (int it = tid; it < NPG*C4; it += 128) {
            int d = it / C4, c4 = (it % C4)*4;
            int s0 = stS[d], s1 = stS[d+1];
            float4 acc = make_float4(0.f,0.f,0.f,0.f);
            for (int j = s0; j < s1; j++) {
                float w = eW[j];
                const float4 h = *(const float4*)&hS[(int)srcS[j]*Fo + c4];
                acc.x=fmaf(w,h.x,acc.x); acc.y=fmaf(w,h.y,acc.y);
                acc.z=fmaf(w,h.z,acc.z); acc.w=fmaf(w,h.w,acc.w);
            }
            float inv = 1.0f/(denS[d] + 1e-16f);
            float o0 = fmaxf(acc.x*inv + biasS[c4+0], 0.f);
            float o1 = fmaxf(acc.y*inv + biasS[c4+1], 0.f);
            float o2 = fmaxf(acc.z*inv + biasS[c4+2], 0.f);
            float o3 = fmaxf(acc.w*inv + biasS[c4+3], 0.f);
            oS[d*Fo+c4+0]=o0; oS[d*Fo+c4+1]=o1; oS[d*Fo+c4+2]=o2; oS[d*Fo+c4+3]=o3;
            size_t fb = fbase + d*Fo + c4;
            put2(fh,fl,fb+0,o0); put2(fh,fl,fb+1,o1); put2(fh,fl,fb+2,o2); put2(fh,fl,fb+3,o3);
            if (HNEXT) *(float4*)&hnext[(nb+d)*Fo + c4] = make_float4(o0,o1,o2,o3);
        }
    } else {
        for (int it = tid; it < NPG*Fo; it += 128) {
            int d = it / Fo, c = it % Fo;
            int s0 = stS[d], s1 = stS[d+1];
            float acc = 0.f;
            for (int j = s0; j < s1; j++) acc = fmaf(eW[j], hS[(int)srcS[j]*Fo + c], acc);
            float o = fmaxf(acc/(denS[d]+1e-16f) + biasS[c], 0.f);
            oS[d*Fo + c] = o;
            put2(fh, fl, fbase + d*Fo + c, o);
            if (HNEXT) hnext[(nb+d)*Fo + c] = o;
        }
    }
    __syncthreads();
    if (tid < Fo) {
        float m = oS[tid];
        for (int n = 1; n < NPG; n++) m = fmaxf(m, oS[n*Fo + tid]);
        put2(fh, fl, (size_t)g*KPAD + poolOff + tid, m);
    }
}

// ---------------- unified split-bf16 HMMA GEMM, 3-stage cp.async ring ------
// Tile 128 x BN, 8 warps (2x4), warp tile 64 x (BN/4).
// smem stage: [Ah 10240 | Al 10240 | Bh BN*80 | Bl BN*80]
template<int BN, int KP, int NT, bool OUTBF16>
__global__ __launch_bounds__(256) void hmma_kernel(
    const __nv_bfloat16* __restrict__ Ah, const __nv_bfloat16* __restrict__ Al,
    const __nv_bfloat16* __restrict__ Bh, const __nv_bfloat16* __restrict__ Bl,
    const float* __restrict__ bias,
    float* __restrict__ Cf, __nv_bfloat16* __restrict__ Ch, __nv_bfloat16* __restrict__ Cl,
    int ldc)
{
    constexpr int WN  = BN/4;          // warp N tile (64 or 32)
    constexpr int NI  = WN/16;         // ldsm x4 B iters
    constexpr int N8  = WN/8;          // mma n8 blocks per warp
    constexpr uint32_t A_B   = 10240;
    constexpr uint32_t BH_O  = 20480;
    constexpr uint32_t BL_O  = BH_O + (uint32_t)BN*80;
    constexpr uint32_t STAGE = BL_O + (uint32_t)BN*80;

    extern __shared__ __align__(128) char sm[];
    const uint32_t sb = smem_u32(sm);
    const int tid = threadIdx.x, lane = tid & 31, w = tid >> 5;
    const int wm = w >> 2, wn = w & 3;
    const int m0 = blockIdx.y * 128, n0 = blockIdx.x * BN;

    auto loadK = [&](int t, int st) {
        const uint32_t base = sb + (uint32_t)st*STAGE;
        const size_t k0 = (size_t)t * 32;
        #pragma unroll
        for (int i = 0; i < 2; i++) {                 // A: 128 rows x 4 chunks
            int idx = tid + i*256;
            int r = idx >> 2, q = idx & 3;
            uint32_t so = (uint32_t)(r*80 + q*16);
            size_t go = (size_t)(m0 + r)*KP + k0 + q*8;
            CP_ASYNC16(base + so,        Ah + go);
            CP_ASYNC16(base + A_B + so,  Al + go);
        }
        #pragma unroll
        for (int i = 0; i < BN/64; i++) {             // B: BN rows x 4 chunks
            int idx = tid + i*256;
            int r = idx >> 2, q = idx & 3;
            uint32_t so = (uint32_t)(r*80 + q*16);
            size_t go = (size_t)(n0 + r)*KP + k0 + q*8;
            CP_ASYNC16(base + BH_O + so, Bh + go);
            CP_ASYNC16(base + BL_O + so, Bl + go);
        }
        CP_COMMIT();
    };

    float acc[4][N8][4];
    #pragma unroll
    for (int i = 0; i < 4; i++)
        #pragma unroll
        for (int j = 0; j < N8; j++)
            #pragma unroll
            for (int k = 0; k < 4; k++) acc[i][j][k] = 0.f;

    loadK(0, 0); loadK(1, 1);

    for (int t = 0; t < NT; t++) {
        const int st = t % 3;
        const uint32_t base = sb + (uint32_t)st*STAGE;
        CP_WAIT(1);
        __syncthreads();
        if (t + 2 < NT) loadK(t + 2, (t + 2) % 3);

        #pragma unroll
        for (int kk = 0; kk < 2; kk++) {
            uint32_t ah[4][4], al[4][4], bh[NI][4], bl[NI][4];
            #pragma unroll
            for (int mi = 0; mi < 4; mi++) {
                int row = wm*64 + mi*16 + (lane & 15);
                uint32_t off = (uint32_t)(row*80 + (kk*16 + (lane >> 4)*8)*2);
                LDSM4(ah[mi], base + off);
                LDSM4(al[mi], base + A_B + off);
            }
            #pragma unroll
            for (int ni = 0; ni < NI; ni++) {
                int nrow = wn*WN + ni*16 + (lane & 7) + ((lane >> 4) & 1)*8;
                uint32_t off = (uint32_t)(nrow*80 + (kk*16 + ((lane >> 3) & 1)*8)*2);
                LDSM4(bh[ni], base + BH_O + off);
                LDSM4(bl[ni], base + BL_O + off);
            }
            #pragma unroll
            for (int mi = 0; mi < 4; mi++) {
                #pragma unroll
                for (int n8 = 0; n8 < N8; n8++) {
                    uint32_t* bhp = &bh[n8 >> 1][(n8 & 1)*2];
                    uint32_t* blp = &bl[n8 >> 1][(n8 & 1)*2];
                    MMA_BF16(acc[mi][n8], ah[mi], bhp);
                    MMA_BF16(acc[mi][n8], ah[mi], blp);
                    MMA_BF16(acc[mi][n8], al[mi], bhp);
                }
            }
        }
    }

    #pragma unroll
    for (int mi = 0; mi < 4; mi++) {
        #pragma unroll
        for (int n8 = 0; n8 < N8; n8++) {
            int col = n0 + wn*WN + n8*8 + (lane & 3)*2;
            float b0 = bias[col], b1 = bias[col + 1];
            #pragma unroll
            for (int h = 0; h < 2; h++) {
                size_t row = (size_t)(m0 + wm*64 + mi*16 + (lane >> 2) + h*8);
                float v0 = fmaxf(acc[mi][n8][h*2+0] + b0, 0.f);
                float v1 = fmaxf(acc[mi][n8][h*2+1] + b1, 0.f);
                if (OUTBF16) {
                    size_t o = row*(size_t)ldc + col;
                    __nv_bfloat16 h0 = __float2bfloat16(v0);
                    __nv_bfloat16 h1v = __float2bfloat16(v1);
                    __nv_bfloat162 ph; ph.x = h0; ph.y = h1v;
                    *(__nv_bfloat162*)&Ch[o] = ph;
                    __nv_bfloat162 pl;
                    pl.x = __float2bfloat16(v0 - __bfloat162float(h0));
                    pl.y = __float2bfloat16(v1 - __bfloat162float(h1v));
                    *(__nv_bfloat162*)&Cl[o] = pl;
                } else {
                    float2 v; v.x = v0; v.y = v1;
                    *(float2*)&Cf[row*(size_t)ldc + col] = v;
                }
            }
        }
    }
}

#define MM1_SMEM (3*(20480 + 2*256*80))   /* 184320 */
#define MM2_SMEM (3*(20480 + 2*128*80))   /* 122880 */

// ---------------- tiny final GEMM ------------------------------------------
__global__ void gemm3_kernel(const float* __restrict__ A, const float* __restrict__ W,
                             const float* __restrict__ bias, float* __restrict__ C)
{
    int idx = blockIdx.x*blockDim.x + threadIdx.x;
    if (idx >= B_GR*9) return;
    int r = idx / 9, c = idx % 9;
    const float* a = A + (long)r*128;
    float acc = bias[c];
    #pragma unroll 8
    for (int k = 0; k < 128; k++) acc = fmaf(a[k], W[k*9 + c], acc);
    C[idx] = acc;
}

// ---------------- launcher -------------------------------------------------
extern "C" void kernel_launch(void* const* d_in, const int* in_sizes, int n_in,
                              void* d_out, int out_size)
{
    (void)in_sizes; (void)n_in; (void)out_size;
    __nv_bfloat16 *fh, *fl, *bth, *btl, *bt2h, *bt2l, *h1h, *h1l;
    float *h2, *ha, *hb, *sn, *dn;
    unsigned char *csrc, *cdst;
    unsigned short *cstart;
    cudaGetSymbolAddress((void**)&fh,   g_fh);
    cudaGetSymbolAddress((void**)&fl,   g_fl);
    cudaGetSymbolAddress((void**)&bth,  g_bth);
    cudaGetSymbolAddress((void**)&btl,  g_btl);
    cudaGetSymbolAddress((void**)&bt2h, g_bt2h);
    cudaGetSymbolAddress((void**)&bt2l, g_bt2l);
    cudaGetSymbolAddress((void**)&h1h,  g_h1h);
    cudaGetSymbolAddress((void**)&h1l,  g_h1l);
    cudaGetSymbolAddress((void**)&h2,   g_h2);
    cudaGetSymbolAddress((void**)&ha,   g_ha);
    cudaGetSymbolAddress((void**)&hb,   g_hb);
    cudaGetSymbolAddress((void**)&sn,   g_sn);
    cudaGetSymbolAddress((void**)&dn,   g_dn);
    cudaGetSymbolAddress((void**)&csrc, g_csrc);
    cudaGetSymbolAddress((void**)&cdst, g_cdst);
    cudaGetSymbolAddress((void**)&cstart, g_cstart);

    cudaFuncSetAttribute((const void*)hmma_kernel<256,4608,144,true>,
                         cudaFuncAttributeMaxDynamicSharedMemorySize, MM1_SMEM);
    cudaFuncSetAttribute((const void*)hmma_kernel<128,1024,32,false>,
                         cudaFuncAttributeMaxDynamicSharedMemorySize, MM2_SMEM);

    const float* x = (const float*)d_in[0];

    detect_kernel<<<1, 128>>>((const unsigned*)d_in[1]);
    prep_kernel<<<B_GR, 64>>>(x, d_in[1], csrc, cdst, cstart, fh, fl);
    tsplit_kernel<FDIM,1024,KPAD><<<dim3(1024/32, (FDIM+31)/32), dim3(32, 8)>>>(
        (const float*)d_in[19], bth, btl);
    tsplit_kernel<1024,128,1024><<<dim3(128/32, 1024/32), dim3(32, 8)>>>(
        (const float*)d_in[21], bt2h, bt2l);

    // layer 1: 1 -> 8
    layerA_kernel<1,8><<<N_TOT/128, 256>>>(x, (const float*)d_in[3],
        (const float*)d_in[4], (const float*)d_in[5], ha, sn, dn);
    layerB_kernel<8,true><<<B_GR, 128>>>(ha, sn, dn, csrc, cdst, cstart,
        (const float*)d_in[6], hb, fh, fl, 39, 4447);
    // layer 2: 8 -> 64
    layerA_kernel<8,64><<<N_TOT/128, 256>>>(hb, (const float*)d_in[7],
        (const float*)d_in[8], (const float*)d_in[9], ha, sn, dn);
    layerB_kernel<64,true><<<B_GR, 128>>>(ha, sn, dn, csrc, cdst, cstart,
        (const float*)d_in[10], hb, fh, fl, 351, 4455);
    // layer 3: 64 -> 32
    layerA_kernel<64,32><<<N_TOT/128, 256>>>(hb, (const float*)d_in[11],
        (const float*)d_in[12], (const float*)d_in[13], ha, sn, dn);
    layerB_kernel<32,true><<<B_GR, 128>>>(ha, sn, dn, csrc, cdst, cstart,
        (const float*)d_in[14], hb, fh, fl, 2847, 4519);
    // layer 4: 32 -> 9
    layerA_kernel<32,9><<<N_TOT/128, 256>>>(hb, (const float*)d_in[15],
        (const float*)d_in[16], (const float*)d_in[17], ha, sn, dn);
    layerB_kernel<9,false><<<B_GR, 128>>>(ha, sn, dn, csrc, cdst, cstart,
        (const float*)d_in[18], hb, fh, fl, 4095, 4551);

    // GEMM1 (HMMA split-bf16, 128x256 tiles): h1 = relu(f @ lw1 + lb1), bf16 hi/lo out
    hmma_kernel<256,4608,144,true><<<dim3(1024/256, B_GR/128), 256, MM1_SMEM>>>(
        fh, fl, bth, btl, (const float*)d_in[20], nullptr, h1h, h1l, 1024);
    // GEMM2 (HMMA split-bf16, 128x128 tiles): h2 = relu(h1 @ lw2 + lb2), fp32 out
    hmma_kernel<128,1024,32,false><<<dim3(128/128, B_GR/128), 256, MM2_SMEM>>>(
        h1h, h1l, bt2h, bt2l, (const float*)d_in[22], h2, nullptr, nullptr, 128);
    // GEMM3: out = h2 @ lw3 + lb3
    gemm3_kernel<<<(B_GR*9 + 255)/256, 256>>>(
        h2, (const float*)d_in[23], (const float*)d_in[24], (float*)d_out);
}

// round 15
// speedup vs baseline: 1.0254x; 1.0254x over previous
#include <cuda_runtime.h>
#include <cuda_bf16.h>
#include <cstdint>

#define B_GR   8192
#define NPG    39
#define N_TOT  (B_GR*NPG)
#define DEG    8
#define EPG    (NPG*DEG)          /* 312 */
#define E_TOT  (N_TOT*DEG)        /* 2555904 */
#define TE     (EPG+NPG)          /* 351 */
#define FDIM   4560
#define KPAD   4608

// ---------------- scratch (static device globals, zero-initialized) -------
__device__ __align__(256) __nv_bfloat16 g_fh [(size_t)B_GR*KPAD];
__device__ __align__(256) __nv_bfloat16 g_fl [(size_t)B_GR*KPAD];
__device__ __align__(256) __nv_bfloat16 g_bth[(size_t)1024*KPAD];
__device__ __align__(256) __nv_bfloat16 g_btl[(size_t)1024*KPAD];
__device__ __align__(256) __nv_bfloat16 g_bt2h[(size_t)128*1024];
__device__ __align__(256) __nv_bfloat16 g_bt2l[(size_t)128*1024];
__device__ __align__(256) __nv_bfloat16 g_h1h[(size_t)B_GR*1024];
__device__ __align__(256) __nv_bfloat16 g_h1l[(size_t)B_GR*1024];
__device__ __align__(256) float g_h2[(size_t)B_GR*128];
__device__ __align__(256) float g_ha[(size_t)N_TOT*64];
__device__ __align__(256) float g_hb[(size_t)N_TOT*64];
__device__ __align__(256) float g_sn[N_TOT];
__device__ __align__(256) float g_dn[N_TOT];
__device__ __align__(256) unsigned char  g_csrc[(size_t)B_GR*352];
__device__ __align__(256) unsigned char  g_cdst[(size_t)B_GR*352];
__device__ __align__(256) unsigned short g_cstart[(size_t)B_GR*40];
__device__ int   g_is64;

// ---------------- PTX helpers (baseline sm_80-class only) ------------------
__device__ __forceinline__ uint32_t smem_u32(const void* p) {
    uint32_t a;
    asm("{ .reg .u64 t; cvta.to.shared.u64 t, %1; cvt.u32.u64 %0, t; }" : "=r"(a) : "l"(p));
    return a;
}
#define CP_ASYNC16(sa, ga) \
    asm volatile("cp.async.cg.shared.global [%0], [%1], 16;" :: "r"(sa), "l"(ga))
#define CP_COMMIT()  asm volatile("cp.async.commit_group;" ::: "memory")
#define CP_WAIT(n)   asm volatile("cp.async.wait_group %0;" :: "n"(n) : "memory")

#define LDSM4(r, addr) \
    asm volatile("ldmatrix.sync.aligned.m8n8.x4.shared.b16 {%0,%1,%2,%3}, [%4];" \
        : "=r"((r)[0]), "=r"((r)[1]), "=r"((r)[2]), "=r"((r)[3]) : "r"(addr))

#define MMA_BF16(acc, a, b) \
    asm volatile("mma.sync.aligned.m16n8k16.row.col.f32.bf16.bf16.f32 " \
        "{%0,%1,%2,%3}, {%4,%5,%6,%7}, {%8,%9}, {%0,%1,%2,%3};" \
        : "+f"((acc)[0]), "+f"((acc)[1]), "+f"((acc)[2]), "+f"((acc)[3]) \
        : "r"((a)[0]), "r"((a)[1]), "r"((a)[2]), "r"((a)[3]), \
          "r"((b)[0]), "r"((b)[1]))

__device__ __forceinline__ void put2(__nv_bfloat16* fh, __nv_bfloat16* fl, size_t idx, float v) {
    __nv_bfloat16 h = __float2bfloat16(v);
    fh[idx] = h;
    fl[idx] = __float2bfloat16(v - __bfloat162float(h));
}

// ---------------- edge dtype detection ------------------------------------
__global__ void detect_kernel(const unsigned* __restrict__ e) {
    int any = __syncthreads_or(e[2*threadIdx.x + 1] != 0u);
    if (threadIdx.x == 0) g_is64 = any ? 0 : 1;
}

// ---------------- transpose + split W[KDIM,NDIM] -> out[NDIM,KP] hi/lo -----
template<int KDIM, int NDIM, int KP>
__global__ __launch_bounds__(256) void tsplit_kernel(const float* __restrict__ W,
                                                     __nv_bfloat16* __restrict__ bh,
                                                     __nv_bfloat16* __restrict__ bl) {
    __shared__ __align__(16) float tile[32][33];
    int kb = blockIdx.y * 32, nb = blockIdx.x * 32;
    int tx = threadIdx.x, ty = threadIdx.y;
    for (int i = ty; i < 32; i += 8) {
        int k = kb + i;
        tile[i][tx] = (k < KDIM) ? W[(size_t)k*NDIM + nb + tx] : 0.f;
    }
    __syncthreads();
    for (int i = ty; i < 32; i += 8) {
        int n = nb + i, k = kb + tx;
        if (k < KDIM) put2(bh, bl, (size_t)n*KP + k, tile[tx][i]);
    }
}

// ---------------- prep: CSR build (deterministic) + res0/pool0 -------------
__global__ __launch_bounds__(64) void prep_kernel(
    const float* __restrict__ x, const void* __restrict__ edges,
    unsigned char* __restrict__ csrc, unsigned char* __restrict__ cdst,
    unsigned short* __restrict__ cstart,
    __nv_bfloat16* __restrict__ fh, __nv_bfloat16* __restrict__ fl)
{
    __shared__ __align__(16) unsigned char es[TE], ed[TE];
    __shared__ __align__(16) int cnt[NPG];
    __shared__ __align__(16) unsigned short st[NPG+1];
    const int g = blockIdx.x, tid = threadIdx.x;
    const int is64 = g_is64;
    const long ebase = (long)g*EPG;
    if (tid < NPG) cnt[tid] = 0;
    for (int i = tid; i < EPG; i += 64) {
        int s, d;
        if (is64) { const long long* e=(const long long*)edges; s=(int)e[ebase+i]; d=(int)e[(long)E_TOT+ebase+i]; }
        else      { const int* e=(const int*)edges; s=e[ebase+i]; d=e[(long)E_TOT+ebase+i]; }
        es[i]=(unsigned char)(s-g*NPG); ed[i]=(unsigned char)(d-g*NPG);
    }
    for (int i = EPG+tid; i < TE; i += 64) { es[i]=ed[i]=(unsigned char)(i-EPG); }
    __syncthreads();
    for (int i = tid; i < TE; i += 64) atomicAdd(&cnt[ed[i]], 1);
    __syncthreads();
    if (tid == 0) {
        int run = 0;
        for (int d = 0; d < NPG; d++) { st[d]=(unsigned short)run; run += cnt[d]; }
        st[NPG] = (unsigned short)run;
    }
    __syncthreads();
    if (tid < NPG) {                     // deterministic scatter per dst
        int pos = st[tid];
        for (int i = 0; i < TE; i++)
            if (ed[i] == (unsigned char)tid) {
                csrc[(size_t)g*352 + pos] = es[i];
                cdst[(size_t)g*352 + pos] = (unsigned char)tid;
                pos++;
            }
    }
    if (tid < NPG+1) cstart[(size_t)g*40 + tid] = st[tid];
    if (tid < NPG)   put2(fh, fl, (size_t)g*KPAD + tid, x[g*NPG + tid]);
    if (tid == 0) {
        float m = x[g*NPG];
        for (int n = 1; n < NPG; n++) m = fmaxf(m, x[g*NPG + n]);
        put2(fh, fl, (size_t)g*KPAD + 4446, m);
    }
}

// ---------------- layer A: dense H = hprev @ W, s/d logits -----------------
template<int Fi, int Fo>
__global__ __launch_bounds__(256) void layerA_kernel(
    const float* __restrict__ hprev, const float* __restrict__ W,
    const float* __restrict__ a_s, const float* __restrict__ a_d,
    float* __restrict__ H, float* __restrict__ sN, float* __restrict__ dN)
{
    constexpr int NB = 128;
    __shared__ __align__(16) float wS[Fi*Fo];
    __shared__ __align__(16) float asS[Fo];
    __shared__ __align__(16) float adS[Fo];
    __shared__ __align__(16) float xS[NB*Fi];
    __shared__ __align__(16) float htmp[(Fo % 4 == 0) ? 4 : NB*Fo];
    const int tid = threadIdx.x;
    const size_t n0 = (size_t)blockIdx.x * NB;

    for (int i = tid; i < Fi*Fo; i += 256) wS[i] = W[i];
    if (tid < Fo) { asS[tid] = a_s[tid]; adS[tid] = a_d[tid]; }
    for (int i = tid; i < NB*Fi/4; i += 256)
        *(float4*)&xS[i*4] = *(const float4*)&hprev[n0*Fi + i*4];
    __syncthreads();

    if constexpr (Fo % 4 == 0) {
        constexpr int C4 = Fo/4;
        const int lane = tid & 31;
        for (int it = tid; it < NB*C4; it += 256) {
            int n = it / C4, c4 = (it % C4)*4;
            float4 acc = make_float4(0.f,0.f,0.f,0.f);
            #pragma unroll
            for (int ci = 0; ci < Fi; ci++) {
                float a = xS[n*Fi + ci];
                const float4 w = *(const float4*)&wS[ci*Fo + c4];
                acc.x=fmaf(a,w.x,acc.x); acc.y=fmaf(a,w.y,acc.y);
                acc.z=fmaf(a,w.z,acc.z); acc.w=fmaf(a,w.w,acc.w);
            }
            *(float4*)&H[(n0+n)*Fo + c4] = acc;
            float sp = acc.x*asS[c4] + acc.y*asS[c4+1] + acc.z*asS[c4+2] + acc.w*asS[c4+3];
            float dp = acc.x*adS[c4] + acc.y*adS[c4+1] + acc.z*adS[c4+2] + acc.w*adS[c4+3];
            #pragma unroll
            for (int off = C4/2; off > 0; off >>= 1) {
                sp += __shfl_xor_sync(0xffffffffu, sp, off);
                dp += __shfl_xor_sync(0xffffffffu, dp, off);
            }
            if ((lane & (C4-1)) == 0) { sN[n0+n] = sp; dN[n0+n] = dp; }
        }
    } else {
        for (int it = tid; it < NB*Fo; it += 256) {
            int n = it / Fo, c = it % Fo;
            float acc = 0.f;
            #pragma unroll
            for (int ci = 0; ci < Fi; ci++) acc = fmaf(xS[n*Fi+ci], wS[ci*Fo+c], acc);
            H[(n0+n)*Fo + c] = acc;
            htmp[n*Fo + c] = acc;
        }
        __syncthreads();
        if (tid < NB) {
            float s = 0.f, d = 0.f;
            #pragma unroll
            for (int c = 0; c < Fo; c++) { float v = htmp[tid*Fo+c]; s = fmaf(v, asS[c], s); d = fmaf(v, adS[c], d); }
            sN[n0+tid] = s; dN[n0+tid] = d;
        }
    }
}

// ---------------- layer B: per-graph softmax + aggregate -------------------
template<int Fo, bool HNEXT>
__global__ __launch_bounds__(128) void layerB_kernel(
    const float* __restrict__ H, const float* __restrict__ sN, const float* __restrict__ dN,
    const unsigned char* __restrict__ csrc, const unsigned char* __restrict__ cdst,
    const unsigned short* __restrict__ cstart,
    const float* __restrict__ bvec, float* __restrict__ hnext,
    __nv_bfloat16* __restrict__ fh, __nv_bfloat16* __restrict__ fl,
    int resOff, int poolOff)
{
    __shared__ __align__(16) float hS[NPG*Fo];
    __shared__ __align__(16) float oS[NPG*Fo];
    __shared__ __align__(16) float eW[TE];
    __shared__ __align__(16) float snS[NPG];
    __shared__ __align__(16) float dnS[NPG];
    __shared__ __align__(16) float denS[NPG];
    __shared__ __align__(16) float biasS[Fo];
    __shared__ __align__(16) unsigned char srcS[TE];
    __shared__ __align__(16) unsigned char dstS[TE];
    __shared__ __align__(16) unsigned short stS[NPG+1];
    const int tid = threadIdx.x;
    const int g = blockIdx.x;
    const size_t nb = (size_t)g * NPG;

    if constexpr (Fo % 4 == 0) {
        for (int i = tid; i < NPG*Fo/4; i += 128)
            *(float4*)&hS[i*4] = *(const float4*)&H[nb*Fo + i*4];
    } else {
        for (int i = tid; i < NPG*Fo; i += 128) hS[i] = H[nb*Fo + i];
    }
    if (tid < NPG)   { snS[tid] = sN[nb+tid]; dnS[tid] = dN[nb+tid]; }
    if (tid < Fo)    biasS[tid] = bvec[tid];
    if (tid < NPG+1) stS[tid] = cstart[(size_t)g*40 + tid];
    for (int i = tid; i < TE; i += 128) {
        srcS[i] = csrc[(size_t)g*352 + i];
        dstS[i] = cdst[(size_t)g*352 + i];
    }
    __syncthreads();

    for (int i = tid; i < TE; i += 128) {
        float e = snS[srcS[i]] + dnS[dstS[i]];
        eW[i] = e > 0.f ? e : 0.2f*e;
    }
    __syncthreads();

    if (tid < NPG) {
        int s0 = stS[tid], s1 = stS[tid+1];
        float m = -3.0e38f;
        for (int j = s0; j < s1; j++) m = fmaxf(m, eW[j]);
        float dd = 0.f;
        for (int j = s0; j < s1; j++) { float w = __expf(eW[j] - m); eW[j] = w; dd += w; }
        denS[tid] = dd;
    }
    __syncthreads();

    const size_t fbase = (size_t)g*KPAD + resOff;
    if constexpr (Fo % 4 == 0) {
        constexpr int C4 = Fo/4;
        for (int it = tid; it < NPG*C4; it += 128) {
            int d = it / C4, c4 = (it % C4)*4;
            int s0 = stS[d], s1 = stS[d+1];
            float4 acc = make_float4(0.f,0.f,0.f,0.f);
            for (int j = s0; j < s1; j++) {
                float w = eW[j];
                const float4 h = *(const float4*)&hS[(int)srcS[j]*Fo + c4];
                acc.x=fmaf(w,h.x,acc.x); acc.y=fmaf(w,h.y,acc.y);
                acc.z=fmaf(w,h.z,acc.z); acc.w=fmaf(w,h.w,acc.w);
            }
            float inv = 1.0f/(denS[d] + 1e-16f);
            float o0 = fmaxf(acc.x*inv + biasS[c4+0], 0.f);
            float o1 = fmaxf(acc.y*inv + biasS[c4+1], 0.f);
            float o2 = fmaxf(acc.z*inv + biasS[c4+2], 0.f);
            float o3 = fmaxf(acc.w*inv + biasS[c4+3], 0.f);
            oS[d*Fo+c4+0]=o0; oS[d*Fo+c4+1]=o1; oS[d*Fo+c4+2]=o2; oS[d*Fo+c4+3]=o3;
            size_t fb = fbase + d*Fo + c4;
            put2(fh,fl,fb+0,o0); put2(fh,fl,fb+1,o1); put2(fh,fl,fb+2,o2); put2(fh,fl,fb+3,o3);
            if (HNEXT) *(float4*)&hnext[(nb+d)*Fo + c4] = make_float4(o0,o1,o2,o3);
        }
    } else {
        for (int it = tid; it < NPG*Fo; it += 128) {
            int d = it / Fo, c = it % Fo;
            int s0 = stS[d], s1 = stS[d+1];
            float acc = 0.f;
            for (int j = s0; j < s1; j++) acc = fmaf(eW[j], hS[(int)srcS[j]*Fo + c], acc);
            float o = fmaxf(acc/(denS[d]+1e-16f) + biasS[c], 0.f);
            oS[d*Fo + c] = o;
            put2(fh, fl, fbase + d*Fo + c, o);
            if (HNEXT) hnext[(nb+d)*Fo + c] = o;
        }
    }
    __syncthreads();
    if (tid < Fo) {
        float m = oS[tid];
        for (int n = 1; n < NPG; n++) m = fmaxf(m, oS[n*Fo + tid]);
        put2(fh, fl, (size_t)g*KPAD + poolOff + tid, m);
    }
}

// ---------------- unified split-bf16 HMMA GEMM, 2-stage, 2 CTAs/SM ---------
// Tile 128 x BN, 8 warps (2x4), warp tile 64 x (BN/4).
// smem stage: [Ah 10240 | Al 10240 | Bh BN*80 | Bl BN*80]
template<int BN, int KP, int NT, bool OUTBF16>
__global__ __launch_bounds__(256, 2) void hmma_kernel(
    const __nv_bfloat16* __restrict__ Ah, const __nv_bfloat16* __restrict__ Al,
    const __nv_bfloat16* __restrict__ Bh, const __nv_bfloat16* __restrict__ Bl,
    const float* __restrict__ bias,
    float* __restrict__ Cf, __nv_bfloat16* __restrict__ Ch, __nv_bfloat16* __restrict__ Cl,
    int ldc)
{
    constexpr int WN  = BN/4;          // warp N tile (32 or 16)
    constexpr int NI  = WN/16;         // ldsm x4 B iters
    constexpr int N8  = WN/8;          // mma n8 blocks per warp
    constexpr uint32_t A_B   = 10240;
    constexpr uint32_t BH_O  = 20480;
    constexpr uint32_t BL_O  = BH_O + (uint32_t)BN*80;
    constexpr uint32_t STAGE = BL_O + (uint32_t)BN*80;

    extern __shared__ __align__(128) char sm[];
    const uint32_t sb = smem_u32(sm);
    const int tid = threadIdx.x, lane = tid & 31, w = tid >> 5;
    const int wm = w >> 2, wn = w & 3;
    const int m0 = blockIdx.y * 128, n0 = blockIdx.x * BN;

    auto loadK = [&](int t, int st) {
        const uint32_t base = sb + (uint32_t)st*STAGE;
        const size_t k0 = (size_t)t * 32;
        #pragma unroll
        for (int i = 0; i < 2; i++) {                 // A: 128 rows x 4 chunks
            int idx = tid + i*256;
            int r = idx >> 2, q = idx & 3;
            uint32_t so = (uint32_t)(r*80 + q*16);
            size_t go = (size_t)(m0 + r)*KP + k0 + q*8;
            CP_ASYNC16(base + so,        Ah + go);
            CP_ASYNC16(base + A_B + so,  Al + go);
        }
        #pragma unroll
        for (int i = 0; i < (BN + 63)/64; i++) {      // B: BN rows x 4 chunks
            int idx = tid + i*256;
            if (BN == 64 && idx >= 256) break;
            int r = idx >> 2, q = idx & 3;
            if (r < BN) {
                uint32_t so = (uint32_t)(r*80 + q*16);
                size_t go = (size_t)(n0 + r)*KP + k0 + q*8;
                CP_ASYNC16(base + BH_O + so, Bh + go);
                CP_ASYNC16(base + BL_O + so, Bl + go);
            }
        }
        CP_COMMIT();
    };

    float acc[4][N8][4];
    #pragma unroll
    for (int i = 0; i < 4; i++)
        #pragma unroll
        for (int j = 0; j < N8; j++)
            #pragma unroll
            for (int k = 0; k < 4; k++) acc[i][j][k] = 0.f;

    loadK(0, 0);

    for (int t = 0; t < NT; t++) {
        const int buf = t & 1;
        const uint32_t base = sb + (uint32_t)buf*STAGE;
        if (t + 1 < NT) { loadK(t + 1, buf ^ 1); CP_WAIT(1); }
        else            { CP_WAIT(0); }
        __syncthreads();

        #pragma unroll
        for (int kk = 0; kk < 2; kk++) {
            uint32_t ah[4][4], al[4][4], bh[NI][4], bl[NI][4];
            #pragma unroll
            for (int mi = 0; mi < 4; mi++) {
                int row = wm*64 + mi*16 + (lane & 15);
                uint32_t off = (uint32_t)(row*80 + (kk*16 + (lane >> 4)*8)*2);
                LDSM4(ah[mi], base + off);
                LDSM4(al[mi], base + A_B + off);
            }
            #pragma unroll
            for (int ni = 0; ni < NI; ni++) {
                int nrow = wn*WN + ni*16 + (lane & 7) + ((lane >> 4) & 1)*8;
                uint32_t off = (uint32_t)(nrow*80 + (kk*16 + ((lane >> 3) & 1)*8)*2);
                LDSM4(bh[ni], base + BH_O + off);
                LDSM4(bl[ni], base + BL_O + off);
            }
            #pragma unroll
            for (int mi = 0; mi < 4; mi++) {
                #pragma unroll
                for (int n8 = 0; n8 < N8; n8++) {
                    uint32_t* bhp = &bh[n8 >> 1][(n8 & 1)*2];
                    uint32_t* blp = &bl[n8 >> 1][(n8 & 1)*2];
                    MMA_BF16(acc[mi][n8], ah[mi], bhp);
                    MMA_BF16(acc[mi][n8], ah[mi], blp);
                    MMA_BF16(acc[mi][n8], al[mi], bhp);
                }
            }
        }
        __syncthreads();   // all warps done reading buf before t+2 overwrites it
    }

    #pragma unroll
    for (int mi = 0; mi < 4; mi++) {
        #pragma unroll
        for (int n8 = 0; n8 < N8; n8++) {
            int col = n0 + wn*WN + n8*8 + (lane & 3)*2;
            float b0 = bias[col], b1 = bias[col + 1];
            #pragma unroll
            for (int h = 0; h < 2; h++) {
                size_t row = (size_t)(m0 + wm*64 + mi*16 + (lane >> 2) + h*8);
                float v0 = fmaxf(acc[mi][n8][h*2+0] + b0, 0.f);
                float v1 = fmaxf(acc[mi][n8][h*2+1] + b1, 0.f);
                if (OUTBF16) {
                    size_t o = row*(size_t)ldc + col;
                    __nv_bfloat16 h0 = __float2bfloat16(v0);
                    __nv_bfloat16 h1v = __float2bfloat16(v1);
                    __nv_bfloat162 ph; ph.x = h0; ph.y = h1v;
                    *(__nv_bfloat162*)&Ch[o] = ph;
                    __nv_bfloat162 pl;
                    pl.x = __float2bfloat16(v0 - __bfloat162float(h0));
                    pl.y = __float2bfloat16(v1 - __bfloat162float(h1v));
                    *(__nv_bfloat162*)&Cl[o] = pl;
                } else {
                    float2 v; v.x = v0; v.y = v1;
                    *(float2*)&Cf[row*(size_t)ldc + col] = v;
                }
            }
        }
    }
}

#define MM1_SMEM (2*(20480 + 2*128*80))   /* 81920 */
#define MM2_SMEM (2*(20480 + 2*64*80))    /* 61440 */

// ---------------- tiny final GEMM ------------------------------------------
__global__ void gemm3_kernel(const float* __restrict__ A, const float* __restrict__ W,
                             const float* __restrict__ bias, float* __restrict__ C)
{
    int idx = blockIdx.x*blockDim.x + threadIdx.x;
    if (idx >= B_GR*9) return;
    int r = idx / 9, c = idx % 9;
    const float* a = A + (long)r*128;
    float acc = bias[c];
    #pragma unroll 8
    for (int k = 0; k < 128; k++) acc = fmaf(a[k], W[k*9 + c], acc);
    C[idx] = acc;
}

// ---------------- launcher -------------------------------------------------
extern "C" void kernel_launch(void* const* d_in, const int* in_sizes, int n_in,
                              void* d_out, int out_size)
{
    (void)in_sizes; (void)n_in; (void)out_size;
    __nv_bfloat16 *fh, *fl, *bth, *btl, *bt2h, *bt2l, *h1h, *h1l;
    float *h2, *ha, *hb, *sn, *dn;
    unsigned char *csrc, *cdst;
    unsigned short *cstart;
    cudaGetSymbolAddress((void**)&fh,   g_fh);
    cudaGetSymbolAddress((void**)&fl,   g_fl);
    cudaGetSymbolAddress((void**)&bth,  g_bth);
    cudaGetSymbolAddress((void**)&btl,  g_btl);
    cudaGetSymbolAddress((void**)&bt2h, g_bt2h);
    cudaGetSymbolAddress((void**)&bt2l, g_bt2l);
    cudaGetSymbolAddress((void**)&h1h,  g_h1h);
    cudaGetSymbolAddress((void**)&h1l,  g_h1l);
    cudaGetSymbolAddress((void**)&h2,   g_h2);
    cudaGetSymbolAddress((void**)&ha,   g_ha);
    cudaGetSymbolAddress((void**)&hb,   g_hb);
    cudaGetSymbolAddress((void**)&sn,   g_sn);
    cudaGetSymbolAddress((void**)&dn,   g_dn);
    cudaGetSymbolAddress((void**)&csrc, g_csrc);
    cudaGetSymbolAddress((void**)&cdst, g_cdst);
    cudaGetSymbolAddress((void**)&cstart, g_cstart);

    cudaFuncSetAttribute((const void*)hmma_kernel<128,4608,144,true>,
                         cudaFuncAttributeMaxDynamicSharedMemorySize, MM1_SMEM);
    cudaFuncSetAttribute((const void*)hmma_kernel<64,1024,32,false>,
                         cudaFuncAttributeMaxDynamicSharedMemorySize, MM2_SMEM);

    const float* x = (const float*)d_in[0];

    detect_kernel<<<1, 128>>>((const unsigned*)d_in[1]);
    prep_kernel<<<B_GR, 64>>>(x, d_in[1], csrc, cdst, cstart, fh, fl);
    tsplit_kernel<FDIM,1024,KPAD><<<dim3(1024/32, (FDIM+31)/32), dim3(32, 8)>>>(
        (const float*)d_in[19], bth, btl);
    tsplit_kernel<1024,128,1024><<<dim3(128/32, 1024/32), dim3(32, 8)>>>(
        (const float*)d_in[21], bt2h, bt2l);

    // layer 1: 1 -> 8
    layerA_kernel<1,8><<<N_TOT/128, 256>>>(x, (const float*)d_in[3],
        (const float*)d_in[4], (const float*)d_in[5], ha, sn, dn);
    layerB_kernel<8,true><<<B_GR, 128>>>(ha, sn, dn, csrc, cdst, cstart,
        (const float*)d_in[6], hb, fh, fl, 39, 4447);
    // layer 2: 8 -> 64
    layerA_kernel<8,64><<<N_TOT/128, 256>>>(hb, (const float*)d_in[7],
        (const float*)d_in[8], (const float*)d_in[9], ha, sn, dn);
    layerB_kernel<64,true><<<B_GR, 128>>>(ha, sn, dn, csrc, cdst, cstart,
        (const float*)d_in[10], hb, fh, fl, 351, 4455);
    // layer 3: 64 -> 32
    layerA_kernel<64,32><<<N_TOT/128, 256>>>(hb, (const float*)d_in[11],
        (const float*)d_in[12], (const float*)d_in[13], ha, sn, dn);
    layerB_kernel<32,true><<<B_GR, 128>>>(ha, sn, dn, csrc, cdst, cstart,
        (const float*)d_in[14], hb, fh, fl, 2847, 4519);
    // layer 4: 32 -> 9
    layerA_kernel<32,9><<<N_TOT/128, 256>>>(hb, (const float*)d_in[15],
        (const float*)d_in[16], (const float*)d_in[17], ha, sn, dn);
    layerB_kernel<9,false><<<B_GR, 128>>>(ha, sn, dn, csrc, cdst, cstart,
        (const float*)d_in[18], hb, fh, fl, 4095, 4551);

    // GEMM1 (HMMA split-bf16, 128x128, 2 CTAs/SM): h1 = relu(f @ lw1 + lb1), bf16 hi/lo
    hmma_kernel<128,4608,144,true><<<dim3(1024/128, B_GR/128), 256, MM1_SMEM>>>(
        fh, fl, bth, btl, (const float*)d_in[20], nullptr, h1h, h1l, 1024);
    // GEMM2 (HMMA split-bf16, 128x64, 128 CTAs): h2 = relu(h1 @ lw2 + lb2), fp32
    hmma_kernel<64,1024,32,false><<<dim3(128/64, B_GR/128), 256, MM2_SMEM>>>(
        h1h, h1l, bt2h, bt2l, (const float*)d_in[22], h2, nullptr, nullptr, 128);
    // GEMM3: out = h2 @ lw3 + lb3
    gemm3_kernel<<<(B_GR*9 + 255)/256, 256>>>(
        h2, (const float*)d_in[23], (const float*)d_in[24], (float*)d_out);
}